// round 14
// baseline (speedup 1.0000x reference)
#include <cuda_runtime.h>
#include <cuda_fp16.h>
#include <math.h>

#define HID    256
#define NGRAPH 8192
#define NSM    148

// Scratch (allocation-free rule: __device__ globals)
__device__ float g_acc[NGRAPH * HID];   // unnormalized weighted sums
__device__ float g_sum[NGRAPH];         // sum of exp(gate) per graph
__device__ int   g_off[NGRAPH + 1];

__device__ __forceinline__ float tanh_fast(float v) {
    float r;
    asm("tanh.approx.f32 %0, %1;" : "=f"(r) : "f"(v));
    return r;
}

// m16n8k16 f16 mma, fp32 accumulate
__device__ __forceinline__ void mma_f16(float* d, const unsigned* a, unsigned b0, unsigned b1) {
    asm volatile(
        "mma.sync.aligned.m16n8k16.row.col.f32.f16.f16.f32 "
        "{%0,%1,%2,%3}, {%4,%5,%6,%7}, {%8,%9}, {%0,%1,%2,%3};\n"
        : "+f"(d[0]), "+f"(d[1]), "+f"(d[2]), "+f"(d[3])
        : "r"(a[0]), "r"(a[1]), "r"(a[2]), "r"(a[3]), "r"(b0), "r"(b1));
}

__device__ __forceinline__ unsigned pack_h2(float lo, float hi) {
    __half2 h = __floats2half2_rn(lo, hi);   // lo -> low 16 bits (smaller k)
    return *(unsigned*)&h;
}

// smem word layout (dynamic), total 231424 B <= 227 KB:
//   W1p : [128][132]  fp16x2 of W1 packed along k, N-permuted (q=(c&7)*16+(c>>3)).
//         Cols 0..127 hold B data; pad cols 128..131 hold b1 (128), w2 (129),
//         gate partials / exp(gate) (130,131) — never touched by B-fragment loads.
//   xs  : 8 x [128][40] raw fp32 of x chunks — the FULL 128x256 tile resident.
#define W1P_STRIDE 132
#define XS_STRIDE  40
#define XS_WORDS   (128 * XS_STRIDE)
#define SMEM_WORDS (128 * W1P_STRIDE + 8 * XS_WORDS)

// Stage one 128x32 fp32 chunk of x into an xs buffer via cp.async (16B, zero-fill tail)
__device__ __forceinline__ void stage_x(unsigned* xsbuf, const float* __restrict__ x,
                                        int nb, int kc, int N, int tid)
{
    #pragma unroll
    for (int j = 0; j < 4; j++) {
        int idx = tid + j * 256;          // 0..1023
        int r   = idx >> 3;               // row 0..127
        int cw  = (idx & 7) * 4;          // word col 0..28
        int node = nb + r;
        int ok = (node < N);
        const float* src = x + (size_t)(ok ? node : 0) * HID + kc * 32 + cw;
        unsigned daddr = (unsigned)__cvta_generic_to_shared(xsbuf + r * XS_STRIDE + cw);
        int sz = ok ? 16 : 0;
        asm volatile("cp.async.cg.shared.global [%0], [%1], 16, %2;\n"
                     :: "r"(daddr), "l"(src), "r"(sz));
    }
    asm volatile("cp.async.commit_group;\n");
}

__device__ __forceinline__ void stage_tile(unsigned* xsb0, const float* __restrict__ x,
                                           int nb, int N, int tid)
{
    #pragma unroll
    for (int c = 0; c < 8; c++)
        stage_x(xsb0 + c * XS_WORDS, x, nb, c, N, tid);
}

// Dtype-agnostic batch read (JAX x64-off downcasts int64->int32 silently).
__device__ __forceinline__ int batch_at(const void* batch, int i, int is64) {
    if (is64) return (int)((const long long*)batch)[i];
    return ((const int*)batch)[i];
}

__global__ __launch_bounds__(256)
void gate_kernel(const float* __restrict__ x, const float* __restrict__ W1,
                 const float* __restrict__ b1v, const float* __restrict__ W2,
                 const float* __restrict__ b2, const void* __restrict__ batch,
                 int N, int ntiles)
{
    extern __shared__ unsigned smemw[];
    unsigned* W1p  = smemw;                    // 128*132
    unsigned* xsb0 = W1p + 128 * W1P_STRIDE;   // 8 x 128*40
    float*    W1pf = (float*)W1p;

    const int tid  = threadIdx.x;
    const int lane = tid & 31;
    const int warp = tid >> 5;
    const int t    = lane & 3;   // threadID_in_group
    const int g    = lane >> 2;  // groupID
    const int mw   = warp & 3;   // 4 warps along M
    const int nw   = warp >> 2;  // 2 warps along N

    const int is64 = (((const int*)batch)[N - 1] == 0) ? 1 : 0;

    // Stage W1 once per persistent CTA: fp16x2 k-packed + N-permutation
    for (int idx = tid; idx < 128 * 128; idx += 256) {
        int k2 = idx >> 7, c = idx & 127;              // k2 = k/2
        int q = (c & 7) * 16 + (c >> 3);
        W1p[k2 * W1P_STRIDE + q] =
            pack_h2(W1[(2 * k2) * 128 + c], W1[(2 * k2 + 1) * 128 + c]);
    }
    if (tid < 128) {
        W1pf[tid * W1P_STRIDE + 128] = b1v[tid];   // b1
        W1pf[tid * W1P_STRIDE + 129] = W2[tid];    // w2
    }
    const float b2v = b2[0];
    __syncthreads();

    // Per-thread base for vectorized B loads: q = g*16 + nw*8 + nt, nt=0..7
    const int bq = g * 16 + nw * 8;

    // Prologue: full first tile in flight (8 commit groups)
    stage_tile(xsb0, x, blockIdx.x * 128, N, tid);

    for (int tile = blockIdx.x; tile < ntiles; tile += gridDim.x) {
        const int nb = tile * 128;
        const int gg0raw = batch_at(batch, nb, is64);

        float acc[2][8][4];
        #pragma unroll
        for (int mt = 0; mt < 2; mt++)
            #pragma unroll
            for (int nt = 0; nt < 8; nt++)
                #pragma unroll
                for (int i = 0; i < 4; i++) acc[mt][nt][i] = 0.f;

        #pragma unroll
        for (int kc = 0; kc < 8; kc++) {
            switch (kc) {   // chunk kc landed when <= 7-kc groups pending
                case 0:  asm volatile("cp.async.wait_group 7;\n"); break;
                case 1:  asm volatile("cp.async.wait_group 6;\n"); break;
                case 2:  asm volatile("cp.async.wait_group 5;\n"); break;
                case 3:  asm volatile("cp.async.wait_group 4;\n"); break;
                case 4:  asm volatile("cp.async.wait_group 3;\n"); break;
                case 5:  asm volatile("cp.async.wait_group 2;\n"); break;
                case 6:  asm volatile("cp.async.wait_group 1;\n"); break;
                default: asm volatile("cp.async.wait_group 0;\n"); break;
            }
            __syncthreads();

            const float* xsb = (const float*)(xsb0 + kc * XS_WORDS);
            #pragma unroll
            for (int s = 0; s < 2; s++) {
                const int kl = s * 16;
                unsigned a[2][4];
                #pragma unroll
                for (int mt = 0; mt < 2; mt++) {
                    int r0 = mw * 32 + mt * 16 + g;
                    float2 v0 = *(const float2*)(xsb + r0 * XS_STRIDE + kl + 2 * t);
                    float2 v1 = *(const float2*)(xsb + (r0 + 8) * XS_STRIDE + kl + 2 * t);
                    float2 v2 = *(const float2*)(xsb + r0 * XS_STRIDE + kl + 2 * t + 8);
                    float2 v3 = *(const float2*)(xsb + (r0 + 8) * XS_STRIDE + kl + 2 * t + 8);
                    a[mt][0] = pack_h2(v0.x, v0.y);
                    a[mt][1] = pack_h2(v1.x, v1.y);
                    a[mt][2] = pack_h2(v2.x, v2.y);
                    a[mt][3] = pack_h2(v3.x, v3.y);
                }
                const int k2 = kc * 16 + s * 8;
                const uint4* p0 = (const uint4*)(W1p + (k2 + t) * W1P_STRIDE + bq);
                const uint4* p1 = (const uint4*)(W1p + (k2 + t + 4) * W1P_STRIDE + bq);
                uint4 b0lo = p0[0], b0hi = p0[1];
                uint4 b1lo = p1[0], b1hi = p1[1];
                unsigned bv0[8] = {b0lo.x, b0lo.y, b0lo.z, b0lo.w, b0hi.x, b0hi.y, b0hi.z, b0hi.w};
                unsigned bv1[8] = {b1lo.x, b1lo.y, b1lo.z, b1lo.w, b1hi.x, b1hi.y, b1hi.z, b1hi.w};
                #pragma unroll
                for (int nt = 0; nt < 8; nt++) {
                    mma_f16(acc[0][nt], a[0], bv0[nt], bv1[nt]);
                    mma_f16(acc[1][nt], a[1], bv0[nt], bv1[nt]);
                }
            }
        }
        __syncthreads();   // all warps' ring reads done before re-staging

        // Prefetch the ENTIRE next tile now — DMA overlaps epilogue + scatter
        {
            int nxt = tile + gridDim.x;
            if (nxt < ntiles) stage_tile(xsb0, x, nxt * 128, N, tid);
        }

        // Epilogue: gate = tanh(pre + b1) . W2 + b2, partials into W1p pads 2,3
        #pragma unroll
        for (int mt = 0; mt < 2; mt++) {
            float s0 = 0.f, s1 = 0.f;
            #pragma unroll
            for (int nt = 0; nt < 8; nt++) {
                int c = nw * 64 + nt * 8 + 2 * t;
                float bc0 = W1pf[c * W1P_STRIDE + 128], bc1 = W1pf[(c + 1) * W1P_STRIDE + 128];
                float wc0 = W1pf[c * W1P_STRIDE + 129], wc1 = W1pf[(c + 1) * W1P_STRIDE + 129];
                s0 += tanh_fast(acc[mt][nt][0] + bc0) * wc0 + tanh_fast(acc[mt][nt][1] + bc1) * wc1;
                s1 += tanh_fast(acc[mt][nt][2] + bc0) * wc0 + tanh_fast(acc[mt][nt][3] + bc1) * wc1;
            }
            s0 += __shfl_xor_sync(0xffffffffu, s0, 1);
            s0 += __shfl_xor_sync(0xffffffffu, s0, 2);
            s1 += __shfl_xor_sync(0xffffffffu, s1, 1);
            s1 += __shfl_xor_sync(0xffffffffu, s1, 2);
            if (t == 0) {
                int r = mw * 32 + mt * 16 + g;
                W1pf[r * W1P_STRIDE + 130 + nw]       = s0;
                W1pf[(r + 8) * W1P_STRIDE + 130 + nw] = s1;
            }
        }
        __syncthreads();
        // combine + exp into pad col 130 (no max-shift: |gate| <= ~11.4)
        if (tid < 128) {
            float w = __expf(W1pf[tid * W1P_STRIDE + 130]
                           + W1pf[tid * W1P_STRIDE + 131] + b2v);
            W1pf[tid * W1P_STRIDE + 130] = w;
        }
        __syncthreads();

        // Scatter: warp w owns rows [nb+16w, nb+16w+16); lane owns 8 cols
        // (lane*4 .. +3 and +128 .. +3). x re-read via LDG.128 — L2-hot.
        {
            const int ws = nb + warp * 16;
            const int we = min(ws + 16, N);
            if (ws < we) {
                int gg = min(max(gg0raw, 0), NGRAPH - 1);
                while (gg < NGRAPH && g_off[gg + 1] <= ws) gg++;
                while (gg < NGRAPH && g_off[gg] < we) {
                    int s = g_off[gg] > ws ? g_off[gg] : ws;
                    int e = g_off[gg + 1] < we ? g_off[gg + 1] : we;
                    float a0 = 0.f, a1 = 0.f, a2 = 0.f, a3 = 0.f;
                    float c0 = 0.f, c1 = 0.f, c2 = 0.f, c3 = 0.f;
                    float wsum = 0.f;
                    const float* xp = x + (size_t)s * HID + lane * 4;
                    for (int r = s; r < e; r++, xp += HID) {
                        float wv = W1pf[(r - nb) * W1P_STRIDE + 130];   // broadcast
                        float4 v0 = *(const float4*)xp;
                        float4 v1 = *(const float4*)(xp + 128);
                        a0 += wv * v0.x; a1 += wv * v0.y; a2 += wv * v0.z; a3 += wv * v0.w;
                        c0 += wv * v1.x; c1 += wv * v1.y; c2 += wv * v1.z; c3 += wv * v1.w;
                        wsum += wv;
                    }
                    float* dst = g_acc + (size_t)gg * HID + lane * 4;
                    atomicAdd(dst + 0, a0);   atomicAdd(dst + 1, a1);
                    atomicAdd(dst + 2, a2);   atomicAdd(dst + 3, a3);
                    atomicAdd(dst + 128, c0); atomicAdd(dst + 129, c1);
                    atomicAdd(dst + 130, c2); atomicAdd(dst + 131, c3);
                    if (lane == 0) atomicAdd(&g_sum[gg], wsum);
                    gg++;
                }
            }
        }
        // No extra sync: pad cols 130/131 are next written at the next tile's
        // epilogue, which every warp reaches only after the next mainloop's
        // 8 __syncthreads — none of which this warp arrives at before
        // finishing its scatter (program order).
    }
}

// Segment boundaries + zero accumulators in one launch.
__global__ void offsets_kernel(const void* __restrict__ batch, int N)
{
    int i = blockIdx.x * blockDim.x + threadIdx.x;
    int stride = gridDim.x * blockDim.x;
    for (int j = i; j < NGRAPH * HID; j += stride) g_acc[j] = 0.f;
    for (int j = i; j < NGRAPH; j += stride) g_sum[j] = 0.f;
    if (i >= N) return;
    const int is64 = (((const int*)batch)[N - 1] == 0) ? 1 : 0;
    int bc = batch_at(batch, i, is64);
    bc = min(max(bc, 0), NGRAPH - 1);
    int bp;
    if (i == 0) bp = -1;
    else {
        bp = batch_at(batch, i - 1, is64);
        bp = min(max(bp, -1), NGRAPH - 1);
    }
    for (int gg = bp + 1; gg <= bc; gg++) g_off[gg] = i;
    if (i == N - 1)
        for (int gg = bc + 1; gg <= NGRAPH; gg++) g_off[gg] = N;
}

__global__ __launch_bounds__(256)
void normalize_kernel(float* __restrict__ out)
{
    int idx = blockIdx.x * blockDim.x + threadIdx.x;   // 0 .. NGRAPH*HID-1
    float s = g_sum[idx >> 8];
    out[idx] = g_acc[idx] / (s + 1e-16f);
}

__global__ void zero_kernel()
{
    int idx = blockIdx.x * blockDim.x + threadIdx.x;
    int stride = gridDim.x * blockDim.x;
    for (int i = idx; i < NGRAPH * HID; i += stride) g_acc[i] = 0.f;
    for (int i = idx; i < NGRAPH; i += stride) g_sum[i] = 0.f;
}

extern "C" void kernel_launch(void* const* d_in, const int* in_sizes, int n_in,
                              void* d_out, int out_size)
{
    const float* x     = (const float*)d_in[0];
    const float* W1    = (const float*)d_in[1];
    const float* b1    = (const float*)d_in[2];
    const float* W2    = (const float*)d_in[3];
    const float* b2    = (const float*)d_in[4];
    const void*  batch = d_in[5];
    float* out = (float*)d_out;
    const int N = in_sizes[5];

    (void)n_in; (void)out_size;

    cudaFuncSetAttribute(gate_kernel,
                         cudaFuncAttributeMaxDynamicSharedMemorySize,
                         SMEM_WORDS * 4);

    if (N > 0) {
        int ntiles = (N + 127) / 128;
        int gblocks = ntiles < NSM ? ntiles : NSM;
        offsets_kernel<<<(N + 255) / 256, 256>>>(batch, N);   // also zeroes g_acc/g_sum
        gate_kernel<<<gblocks, 256, SMEM_WORDS * 4>>>(x, W1, b1, W2, b2, batch, N, ntiles);
    } else {
        zero_kernel<<<1024, 256>>>();
    }
    normalize_kernel<<<NGRAPH, 256>>>(out);
}

// round 17
// speedup vs baseline: 1.6557x; 1.6557x over previous
#include <cuda_runtime.h>
#include <cuda_fp16.h>
#include <math.h>

#define HID    256
#define NGRAPH 8192
#define NSM    148

// Scratch (allocation-free rule: __device__ globals)
__device__ float g_acc[NGRAPH * HID];   // unnormalized weighted sums
__device__ float g_sum[NGRAPH];         // sum of exp(gate) per graph
__device__ int   g_off[NGRAPH + 1];

__device__ __forceinline__ float tanh_fast(float v) {
    float r;
    asm("tanh.approx.f32 %0, %1;" : "=f"(r) : "f"(v));
    return r;
}

// m16n8k16 f16 mma, fp32 accumulate
__device__ __forceinline__ void mma_f16(float* d, const unsigned* a, unsigned b0, unsigned b1) {
    asm volatile(
        "mma.sync.aligned.m16n8k16.row.col.f32.f16.f16.f32 "
        "{%0,%1,%2,%3}, {%4,%5,%6,%7}, {%8,%9}, {%0,%1,%2,%3};\n"
        : "+f"(d[0]), "+f"(d[1]), "+f"(d[2]), "+f"(d[3])
        : "r"(a[0]), "r"(a[1]), "r"(a[2]), "r"(a[3]), "r"(b0), "r"(b1));
}

__device__ __forceinline__ unsigned pack_h2(float lo, float hi) {
    __half2 h = __floats2half2_rn(lo, hi);   // lo -> low 16 bits (smaller k)
    return *(unsigned*)&h;
}

// smem word layout (dynamic), total 231424 B <= 227 KB:
//   W1p : [128][132]  fp16x2 of W1 packed along k, N-permuted (q=(c&7)*16+(c>>3)).
//         Cols 0..127 hold B data; pad cols 128..131 hold b1 (128), w2 (129),
//         gate partials / exp(gate) (130,131) — never touched by B-fragment loads.
//   xs  : 8 x [128][40] raw fp32 of x chunks — the FULL 128x256 tile resident.
#define W1P_STRIDE 132
#define XS_STRIDE  40
#define XS_WORDS   (128 * XS_STRIDE)
#define SMEM_WORDS (128 * W1P_STRIDE + 8 * XS_WORDS)

// Pair-local staging: pair p (warps p and p+4) stages ITS OWN 32 A-rows
// [32p, 32p+32) of chunk kc. 64 threads x 4 iters = 256 x 16B. One commit
// group per thread; each warp waits only its own groups.
__device__ __forceinline__ void stage_x_pair(unsigned* xsbuf, const float* __restrict__ x,
                                             int nb, int kc, int p, int N, int ptid)
{
    #pragma unroll
    for (int j = 0; j < 4; j++) {
        int idx = ptid + j * 64;          // 0..255
        int rr  = idx >> 3;               // 0..31
        int cw  = (idx & 7) * 4;          // word col 0..28
        int row = 32 * p + rr;
        int node = nb + row;
        int ok = (node < N);
        const float* src = x + (size_t)(ok ? node : 0) * HID + kc * 32 + cw;
        unsigned daddr = (unsigned)__cvta_generic_to_shared(xsbuf + row * XS_STRIDE + cw);
        int sz = ok ? 16 : 0;
        asm volatile("cp.async.cg.shared.global [%0], [%1], 16, %2;\n"
                     :: "r"(daddr), "l"(src), "r"(sz));
    }
    asm volatile("cp.async.commit_group;\n");
}

// Dtype-agnostic batch read (JAX x64-off downcasts int64->int32 silently).
__device__ __forceinline__ int batch_at(const void* batch, int i, int is64) {
    if (is64) return (int)((const long long*)batch)[i];
    return ((const int*)batch)[i];
}

__global__ __launch_bounds__(256)
void gate_kernel(const float* __restrict__ x, const float* __restrict__ W1,
                 const float* __restrict__ b1v, const float* __restrict__ W2,
                 const float* __restrict__ b2, const void* __restrict__ batch,
                 int N, int ntiles)
{
    extern __shared__ unsigned smemw[];
    unsigned* W1p  = smemw;                    // 128*132
    unsigned* xsb0 = W1p + 128 * W1P_STRIDE;   // 8 x 128*40
    float*    W1pf = (float*)W1p;

    const int tid  = threadIdx.x;
    const int lane = tid & 31;
    const int warp = tid >> 5;
    const int t    = lane & 3;   // threadID_in_group
    const int g    = lane >> 2;  // groupID
    const int mw   = warp & 3;   // pair id: warps mw and mw+4 (same SMSP)
    const int nw   = warp >> 2;  // 2 warps along N
    const int ptid = lane + 32 * nw;   // 0..63 within the pair

    const int is64 = (((const int*)batch)[N - 1] == 0) ? 1 : 0;

    // Stage W1 once per persistent CTA: fp16x2 k-packed + N-permutation
    for (int idx = tid; idx < 128 * 128; idx += 256) {
        int k2 = idx >> 7, c = idx & 127;              // k2 = k/2
        int q = (c & 7) * 16 + (c >> 3);
        W1p[k2 * W1P_STRIDE + q] =
            pack_h2(W1[(2 * k2) * 128 + c], W1[(2 * k2 + 1) * 128 + c]);
    }
    if (tid < 128) {
        W1pf[tid * W1P_STRIDE + 128] = b1v[tid];   // b1
        W1pf[tid * W1P_STRIDE + 129] = W2[tid];    // w2
    }
    const float b2v = b2[0];
    __syncthreads();

    // Per-thread base for vectorized B loads: q = g*16 + nw*8 + nt, nt=0..7
    const int bq = g * 16 + nw * 8;

    for (int tile = blockIdx.x; tile < ntiles; tile += gridDim.x) {
        const int nb = tile * 128;
        const int gg0raw = batch_at(batch, nb, is64);

        float acc[2][8][4];
        #pragma unroll
        for (int mt = 0; mt < 2; mt++)
            #pragma unroll
            for (int nt = 0; nt < 8; nt++)
                #pragma unroll
                for (int i = 0; i < 4; i++) acc[mt][nt][i] = 0.f;

        // Pair-local prologue: our 32 rows of chunks 0..3 (4 groups in flight)
        stage_x_pair(xsb0 + 0 * XS_WORDS, x, nb, 0, mw, N, ptid);
        stage_x_pair(xsb0 + 1 * XS_WORDS, x, nb, 1, mw, N, ptid);
        stage_x_pair(xsb0 + 2 * XS_WORDS, x, nb, 2, mw, N, ptid);
        stage_x_pair(xsb0 + 3 * XS_WORDS, x, nb, 3, mw, N, ptid);

        #pragma unroll
        for (int kc = 0; kc < 8; kc++) {
            if (kc + 4 < 8)
                stage_x_pair(xsb0 + (kc + 4) * XS_WORDS, x, nb, kc + 4, mw, N, ptid);
            switch (kc) {   // own groups: oldest pending is chunk kc
                case 0: case 1: case 2: case 3:
                          asm volatile("cp.async.wait_group 4;\n"); break;
                case 4:   asm volatile("cp.async.wait_group 3;\n"); break;
                case 5:   asm volatile("cp.async.wait_group 2;\n"); break;
                case 6:   asm volatile("cp.async.wait_group 1;\n"); break;
                default:  asm volatile("cp.async.wait_group 0;\n"); break;
            }
            // pair-local barrier (64 threads, id 1+mw): both warps of the pair
            // have waited their own groups -> our 32 rows of chunk kc visible.
            asm volatile("bar.sync %0, %1;" :: "r"(1 + mw), "r"(64) : "memory");

            const float* xsb = (const float*)(xsb0 + kc * XS_WORDS);
            #pragma unroll
            for (int s = 0; s < 2; s++) {
                const int kl = s * 16;
                unsigned a[2][4];
                #pragma unroll
                for (int mt = 0; mt < 2; mt++) {
                    int r0 = mw * 32 + mt * 16 + g;
                    float2 v0 = *(const float2*)(xsb + r0 * XS_STRIDE + kl + 2 * t);
                    float2 v1 = *(const float2*)(xsb + (r0 + 8) * XS_STRIDE + kl + 2 * t);
                    float2 v2 = *(const float2*)(xsb + r0 * XS_STRIDE + kl + 2 * t + 8);
                    float2 v3 = *(const float2*)(xsb + (r0 + 8) * XS_STRIDE + kl + 2 * t + 8);
                    a[mt][0] = pack_h2(v0.x, v0.y);
                    a[mt][1] = pack_h2(v1.x, v1.y);
                    a[mt][2] = pack_h2(v2.x, v2.y);
                    a[mt][3] = pack_h2(v3.x, v3.y);
                }
                const int k2 = kc * 16 + s * 8;
                const uint4* p0 = (const uint4*)(W1p + (k2 + t) * W1P_STRIDE + bq);
                const uint4* p1 = (const uint4*)(W1p + (k2 + t + 4) * W1P_STRIDE + bq);
                uint4 b0lo = p0[0], b0hi = p0[1];
                uint4 b1lo = p1[0], b1hi = p1[1];
                unsigned bv0[8] = {b0lo.x, b0lo.y, b0lo.z, b0lo.w, b0hi.x, b0hi.y, b0hi.z, b0hi.w};
                unsigned bv1[8] = {b1lo.x, b1lo.y, b1lo.z, b1lo.w, b1hi.x, b1hi.y, b1hi.z, b1hi.w};
                #pragma unroll
                for (int nt = 0; nt < 8; nt++) {
                    mma_f16(acc[0][nt], a[0], bv0[nt], bv1[nt]);
                    mma_f16(acc[1][nt], a[1], bv0[nt], bv1[nt]);
                }
            }
        }
        __syncthreads();   // all pairs done with mainloop (scatter reads ALL rows)

        // Epilogue: gate = tanh(pre + b1) . W2 + b2, partials into W1p pads 2,3
        #pragma unroll
        for (int mt = 0; mt < 2; mt++) {
            float s0 = 0.f, s1 = 0.f;
            #pragma unroll
            for (int nt = 0; nt < 8; nt++) {
                int c = nw * 64 + nt * 8 + 2 * t;
                float bc0 = W1pf[c * W1P_STRIDE + 128], bc1 = W1pf[(c + 1) * W1P_STRIDE + 128];
                float wc0 = W1pf[c * W1P_STRIDE + 129], wc1 = W1pf[(c + 1) * W1P_STRIDE + 129];
                s0 += tanh_fast(acc[mt][nt][0] + bc0) * wc0 + tanh_fast(acc[mt][nt][1] + bc1) * wc1;
                s1 += tanh_fast(acc[mt][nt][2] + bc0) * wc0 + tanh_fast(acc[mt][nt][3] + bc1) * wc1;
            }
            s0 += __shfl_xor_sync(0xffffffffu, s0, 1);
            s0 += __shfl_xor_sync(0xffffffffu, s0, 2);
            s1 += __shfl_xor_sync(0xffffffffu, s1, 1);
            s1 += __shfl_xor_sync(0xffffffffu, s1, 2);
            if (t == 0) {
                int r = mw * 32 + mt * 16 + g;
                W1pf[r * W1P_STRIDE + 130 + nw]       = s0;
                W1pf[(r + 8) * W1P_STRIDE + 130 + nw] = s1;
            }
        }
        __syncthreads();
        // combine + exp into pad col 130 (no max-shift: |gate| <= ~11.4)
        if (tid < 128) {
            float w = __expf(W1pf[tid * W1P_STRIDE + 130]
                           + W1pf[tid * W1P_STRIDE + 131] + b2v);
            W1pf[tid * W1P_STRIDE + 130] = w;
        }
        __syncthreads();

        // Scatter (smem): warp w owns column chunk w; thread reads col lane of
        // buffer w (conflict-free), wexp broadcast; 1 atomic/thread/segment.
        {
            const unsigned* xcol = xsb0 + warp * XS_WORDS + lane;
            const int col = warp * 32 + lane;
            const int tend = min(nb + 128, N);
            int gg = min(max(gg0raw, 0), NGRAPH - 1);
            while (gg < NGRAPH) {
                int soff = g_off[gg];
                if (soff >= tend) break;
                int eoff = g_off[gg + 1];
                int s = soff > nb ? soff : nb;
                int e = eoff < tend ? eoff : tend;
                if (e > s) {
                    float accv = 0.f, wsum = 0.f;
                    for (int i = s - nb; i < e - nb; i++) {
                        float w  = W1pf[i * W1P_STRIDE + 130];       // broadcast
                        float xv = __uint_as_float(xcol[i * XS_STRIDE]);
                        accv += w * xv;
                        wsum += w;
                    }
                    atomicAdd(&g_acc[(size_t)gg * HID + col], accv);
                    if (tid == 0) atomicAdd(&g_sum[gg], wsum);
                }
                gg++;
            }
        }
        __syncthreads();   // all scatter reads done before next tile's staging
    }
}

// Segment boundaries + zero accumulators in one launch.
__global__ void offsets_kernel(const void* __restrict__ batch, int N)
{
    int i = blockIdx.x * blockDim.x + threadIdx.x;
    int stride = gridDim.x * blockDim.x;
    for (int j = i; j < NGRAPH * HID; j += stride) g_acc[j] = 0.f;
    for (int j = i; j < NGRAPH; j += stride) g_sum[j] = 0.f;
    if (i >= N) return;
    const int is64 = (((const int*)batch)[N - 1] == 0) ? 1 : 0;
    int bc = batch_at(batch, i, is64);
    bc = min(max(bc, 0), NGRAPH - 1);
    int bp;
    if (i == 0) bp = -1;
    else {
        bp = batch_at(batch, i - 1, is64);
        bp = min(max(bp, -1), NGRAPH - 1);
    }
    for (int gg = bp + 1; gg <= bc; gg++) g_off[gg] = i;
    if (i == N - 1)
        for (int gg = bc + 1; gg <= NGRAPH; gg++) g_off[gg] = N;
}

__global__ __launch_bounds__(256)
void normalize_kernel(float* __restrict__ out)
{
    int idx = blockIdx.x * blockDim.x + threadIdx.x;   // 0 .. NGRAPH*HID-1
    float s = g_sum[idx >> 8];
    out[idx] = g_acc[idx] / (s + 1e-16f);
}

__global__ void zero_kernel()
{
    int idx = blockIdx.x * blockDim.x + threadIdx.x;
    int stride = gridDim.x * blockDim.x;
    for (int i = idx; i < NGRAPH * HID; i += stride) g_acc[i] = 0.f;
    for (int i = idx; i < NGRAPH; i += stride) g_sum[i] = 0.f;
}

extern "C" void kernel_launch(void* const* d_in, const int* in_sizes, int n_in,
                              void* d_out, int out_size)
{
    const float* x     = (const float*)d_in[0];
    const float* W1    = (const float*)d_in[1];
    const float* b1    = (const float*)d_in[2];
    const float* W2    = (const float*)d_in[3];
    const float* b2    = (const float*)d_in[4];
    const void*  batch = d_in[5];
    float* out = (float*)d_out;
    const int N = in_sizes[5];

    (void)n_in; (void)out_size;

    cudaFuncSetAttribute(gate_kernel,
                         cudaFuncAttributeMaxDynamicSharedMemorySize,
                         SMEM_WORDS * 4);

    if (N > 0) {
        int ntiles = (N + 127) / 128;
        int gblocks = ntiles < NSM ? ntiles : NSM;
        offsets_kernel<<<(N + 255) / 256, 256>>>(batch, N);   // also zeroes g_acc/g_sum
        gate_kernel<<<gblocks, 256, SMEM_WORDS * 4>>>(x, W1, b1, W2, b2, batch, N, ntiles);
    } else {
        zero_kernel<<<1024, 256>>>();
    }
    normalize_kernel<<<NGRAPH, 256>>>(out);
}